// round 13
// baseline (speedup 1.0000x reference)
#include <cuda_runtime.h>
#include <cuda_fp16.h>
#include <cstdint>

// ===================== problem dims =====================
static constexpr int BATCH = 16384;
static constexpr int H     = 1024;
static constexpr int KTOT  = 2048;    // IN + H
static constexpr int N4    = 4096;    // 4 gates * H

// ===================== tiling =====================
static constexpr int BM = 128;        // batch rows per CTA
static constexpr int BN = 128;        // C cols per CTA = 32 cols x 4 gates (gate-interleaved)
static constexpr int GC = 32;         // gate-cols per CTA
static constexpr int KC = 64;         // K halves per stage (128B rows)
static constexpr int NCHUNK = KTOT / KC;   // 32
static constexpr int STAGES = 3;
static constexpr int NTHREADS = 256;  // 8 warps; 2 CTAs/SM -> 16 warps/SM
static constexpr int A_BYTES = BM * KC * 2;          // 16 KB
static constexpr int B_BYTES = BN * KC * 2;          // 16 KB
static constexpr int STAGE_BYTES = A_BYTES + B_BYTES;// 32 KB
static constexpr int SMEM_DYN = STAGES * STAGE_BYTES; // 98304

// fp16 scratch (device globals: allocation-free)
__device__ __half g_A16[(long long)BATCH * KTOT];   // 64 MB
__device__ __half g_Wt16[(long long)N4 * KTOT];     // 16 MB, [n][k] K-major

// ===================== helpers =====================
__device__ __forceinline__ uint32_t smem_u32(const void* p) {
    uint32_t a;
    asm("{ .reg .u64 t; cvta.to.shared.u64 t, %1; cvt.u32.u64 %0, t; }" : "=r"(a) : "l"(p));
    return a;
}
__device__ __forceinline__ void cp_async16(uint32_t dst, const void* src) {
    asm volatile("cp.async.cg.shared.global [%0], [%1], 16;" :: "r"(dst), "l"(src));
}
__device__ __forceinline__ void ldsm_x4(uint32_t& r0, uint32_t& r1, uint32_t& r2, uint32_t& r3,
                                        uint32_t addr) {
    asm volatile("ldmatrix.sync.aligned.m8n8.x4.shared.b16 {%0,%1,%2,%3}, [%4];"
                 : "=r"(r0), "=r"(r1), "=r"(r2), "=r"(r3) : "r"(addr));
}
__device__ __forceinline__ void mma16816(float& d0, float& d1, float& d2, float& d3,
                                         uint32_t a0, uint32_t a1, uint32_t a2, uint32_t a3,
                                         uint32_t b0, uint32_t b1) {
    asm volatile("mma.sync.aligned.m16n8k16.row.col.f32.f16.f16.f32 "
                 "{%0,%1,%2,%3}, {%4,%5,%6,%7}, {%8,%9}, {%0,%1,%2,%3};"
                 : "+f"(d0), "+f"(d1), "+f"(d2), "+f"(d3)
                 : "r"(a0), "r"(a1), "r"(a2), "r"(a3), "r"(b0), "r"(b1));
}
__device__ __forceinline__ float fsigm(float v) { return 1.0f / (1.0f + __expf(-v)); }
__device__ __forceinline__ float ftanh(float v) { return 2.0f / (1.0f + __expf(-2.0f * v)) - 1.0f; }

// ---- mbarrier primitives (sm_90 portable PTX, valid at sm_100 non-a) ----
#define MBAR_INIT(addr, cnt) \
    asm volatile("mbarrier.init.shared.b64 [%0], %1;" :: "r"((uint32_t)(addr)), "r"((uint32_t)(cnt)) : "memory")
#define MBAR_ARRIVE(addr) \
    asm volatile("mbarrier.arrive.shared.b64 _, [%0];" :: "r"((uint32_t)(addr)) : "memory")
#define CPASYNC_MBAR_ARRIVE(addr) \
    asm volatile("cp.async.mbarrier.arrive.noinc.shared.b64 [%0];" :: "r"((uint32_t)(addr)) : "memory")
#define MBAR_WAIT_PARITY(addr, par) do {                                               \
    uint32_t _mbar = (uint32_t)(addr);                                                 \
    uint32_t _par  = (uint32_t)(par);                                                  \
    uint32_t _done;                                                                    \
    asm volatile("{\n\t.reg .pred p;\n\t"                                              \
        "mbarrier.try_wait.parity.acquire.cta.shared::cta.b64 p, [%1], %2;\n\t"        \
        "selp.b32 %0, 1, 0, p;\n\t}" : "=r"(_done) : "r"(_mbar), "r"(_par) : "memory");\
    if (!_done) {                                                                      \
        asm volatile("{\n\t.reg .pred P1;\n\t"                                         \
        "WL_%=:\n\t"                                                                   \
        "mbarrier.try_wait.parity.acquire.cta.shared::cta.b64 P1, [%0], %1, 0x989680;\n\t" \
        "@P1 bra.uni WD_%=;\n\t"                                                       \
        "bra.uni WL_%=;\n\t"                                                           \
        "WD_%=:\n\t}" :: "r"(_mbar), "r"(_par) : "memory");                            \
    }                                                                                  \
} while (0)

// ===================== merged prologue =====================
// blocks [0, NA): convert A to fp16.  blocks [NA, NA+NW): transpose+convert W.
static constexpr int NA_BLOCKS = (int)(((long long)BATCH * KTOT / 8) / 256);  // 16384
static constexpr int NW_X = N4 / 32;   // 128
static constexpr int NW_Y = KTOT / 32; // 64

__global__ __launch_bounds__(256) void conv_aw(const float* __restrict__ x,
                                               const float* __restrict__ state,
                                               const float* __restrict__ Wx,
                                               const float* __restrict__ Wh) {
    int bid = blockIdx.x;
    if (bid < NA_BLOCKS) {
        long long idx8 = ((long long)bid * 256 + threadIdx.x) * 8;
        int b = (int)(idx8 >> 11);
        int k = (int)(idx8 & 2047);
        const float* src = (k < H) ? (x + (long long)b * H + k)
                                   : (state + (long long)b * H + (k - H));
        float4 f0 = *reinterpret_cast<const float4*>(src);
        float4 f1 = *reinterpret_cast<const float4*>(src + 4);
        __half2 h[4];
        h[0] = __floats2half2_rn(f0.x, f0.y);
        h[1] = __floats2half2_rn(f0.z, f0.w);
        h[2] = __floats2half2_rn(f1.x, f1.y);
        h[3] = __floats2half2_rn(f1.z, f1.w);
        *reinterpret_cast<uint4*>(&g_A16[idx8]) = *reinterpret_cast<uint4*>(h);
    } else {
        __shared__ float tile[32][33];
        int wb = bid - NA_BLOCKS;
        int n0 = (wb % NW_X) * 32;
        int k0 = (wb / NW_X) * 32;
        int tx = threadIdx.x & 31, ty = threadIdx.x >> 5;   // ty 0..7
#pragma unroll
        for (int i = 0; i < 32; i += 8) {
            int k = k0 + ty + i;
            const float* src = (k < H) ? (Wx + (long long)k * N4) : (Wh + (long long)(k - H) * N4);
            tile[ty + i][tx] = src[n0 + tx];
        }
        __syncthreads();
#pragma unroll
        for (int i = 0; i < 32; i += 8) {
            g_Wt16[(long long)(n0 + ty + i) * KTOT + k0 + tx] = __float2half_rn(tile[tx][ty + i]);
        }
    }
}

// ===================== fused LSTM GEMM + gates =====================
// B smem layout (gate-interleaved, BN=128 rows of 64 halves):
//   row r: warpN=r>>5, gate=(r>>3)&3, i=r&7  ->  n = gate*H + c0 + warpN*8 + i
// Warp tile N=32: nb in {0,1} n16 blocks; gate = nb*2 + h2.
// Pipeline: mbarrier full/empty per stage instead of __syncthreads -> warps may
// skew by up to one chunk instead of convoying at a CTA barrier.
__global__ __launch_bounds__(NTHREADS, 2) void lstm_fused(
    const float* __restrict__ cell, const float* __restrict__ bx,
    const float* __restrict__ bh, float* __restrict__ out)
{
    extern __shared__ char smem_raw[];
    __shared__ float bsum[BN];                 // [gate][32] bias
    __shared__ __align__(8) unsigned long long mbars[2 * STAGES];  // full[0..2], empty[0..2]

    const uint32_t sbase = smem_u32(smem_raw);
    const uint32_t mb_full  = smem_u32(&mbars[0]);
    const uint32_t mb_empty = smem_u32(&mbars[STAGES]);
    int tid = threadIdx.x;
    int lane = tid & 31, wid = tid >> 5;
    int warpM = wid >> 2;            // 0..1, 64 rows each
    int warpN = wid & 3;             // 0..3, 8 gate-cols each (x4 gates)
    int m0 = blockIdx.y * BM;
    int c0 = blockIdx.x * GC;

    if (tid < BN) {   // bsum[g*32 + u] = bx[g*H + c0+u] + bh[g*H + c0+u]
        int g = tid >> 5, u = tid & 31;
        bsum[tid] = bx[g * H + c0 + u] + bh[g * H + c0 + u];
    }
    if (tid == 0) {
#pragma unroll
        for (int s = 0; s < STAGES; ++s) {
            MBAR_INIT(mb_full  + s * 8, NTHREADS);
            MBAR_INIT(mb_empty + s * 8, NTHREADS);
        }
    }
    __syncthreads();   // mbarrier init + bsum visible to all

    // --------- stage producer (each thread: 8 cp.async + mbar arrive) ---------
    auto produce = [&](int stage, int c) {
        uint32_t sA = sbase + stage * STAGE_BYTES;
        uint32_t sB = sA + A_BYTES;
        const __half* srcA = g_A16 + (long long)m0 * KTOT + c * KC;
        const __half* srcB = g_Wt16 + c * KC;
#pragma unroll
        for (int i = 0; i < 4; ++i) {           // A: 1024 segs of 16B
            int idx = tid + i * NTHREADS;
            int row = idx >> 3, seg = idx & 7;
            cp_async16(sA + row * 128 + ((seg ^ (row & 7)) * 16),
                       srcA + (long long)row * KTOT + seg * 8);
        }
#pragma unroll
        for (int i = 0; i < 4; ++i) {           // B: 1024 segs
            int idx = tid + i * NTHREADS;
            int r = idx >> 3, seg = idx & 7;
            int gate = (r >> 3) & 3;
            int colc = ((r >> 5) << 3) | (r & 7);
            int n = gate * H + c0 + colc;
            cp_async16(sB + r * 128 + ((seg ^ (r & 7)) * 16),
                       srcB + (long long)n * KTOT + seg * 8);
        }
        CPASYNC_MBAR_ARRIVE(mb_full + stage * 8);
    };

    // prologue: produce chunks 0,1 (stages 0,1)
    produce(0, 0);
    produce(1, 1);

    float acc[4][2][2][4];   // [mi][nb][h2][4]; gate = nb*2 + h2
#pragma unroll
    for (int mi = 0; mi < 4; ++mi)
#pragma unroll
        for (int nb = 0; nb < 2; ++nb)
#pragma unroll
            for (int h2 = 0; h2 < 2; ++h2)
#pragma unroll
                for (int e = 0; e < 4; ++e) acc[mi][nb][h2][e] = 0.0f;

    // lane-fixed address components
    int rowA = warpM * 64 + (lane & 15);              // + mi*16
    int kslA = (lane >> 4);                           // 0/1 -> +8 halves
    int nB   = warpN * 32 + ((lane >> 4) & 1) * 8 + (lane & 7);   // + nb*16
    int kslB = (lane >> 3) & 1;

    auto compute_ks = [&](uint32_t sA, uint32_t sB, int ks) {
        uint32_t a[4][4];
#pragma unroll
        for (int mi = 0; mi < 4; ++mi) {
            int row = rowA + mi * 16;
            int seg = (ks * 2 + kslA) ^ (row & 7);
            ldsm_x4(a[mi][0], a[mi][1], a[mi][2], a[mi][3], sA + row * 128 + seg * 16);
        }
        uint32_t b[2][4];
#pragma unroll
        for (int nb = 0; nb < 2; ++nb) {
            int n = nB + nb * 16;
            int seg = (ks * 2 + kslB) ^ (n & 7);
            ldsm_x4(b[nb][0], b[nb][1], b[nb][2], b[nb][3], sB + n * 128 + seg * 16);
        }
#pragma unroll
        for (int mi = 0; mi < 4; ++mi)
#pragma unroll
            for (int nb = 0; nb < 2; ++nb) {
                mma16816(acc[mi][nb][0][0], acc[mi][nb][0][1], acc[mi][nb][0][2], acc[mi][nb][0][3],
                         a[mi][0], a[mi][1], a[mi][2], a[mi][3], b[nb][0], b[nb][1]);
                mma16816(acc[mi][nb][1][0], acc[mi][nb][1][1], acc[mi][nb][1][2], acc[mi][nb][1][3],
                         a[mi][0], a[mi][1], a[mi][2], a[mi][3], b[nb][2], b[nb][3]);
            }
    };

#pragma unroll 1
    for (int c = 0; c < NCHUNK; ++c) {
        int s = c % STAGES;
        uint32_t sA = sbase + s * STAGE_BYTES;
        uint32_t sB = sA + A_BYTES;

        // wait chunk-c data (ALL threads' copies: 256 cp.async.mbarrier arrivals)
        MBAR_WAIT_PARITY(mb_full + s * 8, (c / STAGES) & 1);

        // ks=0 first: tensor work starts immediately...
        compute_ks(sA, sB, 0);

        // ...then produce chunk c+2 (stage (c+2)%3), overlapped with ks=1..3.
        int cp = c + STAGES - 1;
        if (cp < NCHUNK) {
            int sp = cp % STAGES;
            if (cp >= STAGES)   // stage reuse: wait until all reads of chunk cp-3 done
                MBAR_WAIT_PARITY(mb_empty + sp * 8, (cp / STAGES - 1) & 1);
            produce(sp, cp);
        }

        compute_ks(sA, sB, 1);
        compute_ks(sA, sB, 2);
        compute_ks(sA, sB, 3);

        // my reads of stage s are done (HMMA issue consumed all LDSM results)
        MBAR_ARRIVE(mb_empty + s * 8);
    }

    // --------- register-direct fused gate epilogue ---------
    // gate g = nb*2+h2: gi=(0,0), gj=(0,1), gf=(1,0), go=(1,1)
    int ucol = warpN * 8 + (lane & 3) * 2;
    float bi[2], bj[2], bf[2], bo[2];
#pragma unroll
    for (int e = 0; e < 2; ++e) {
        int u = ucol + e;
        bi[e] = bsum[0  + u];
        bj[e] = bsum[32 + u];
        bf[e] = bsum[64 + u];
        bo[e] = bsum[96 + u];
    }

    int row0 = m0 + warpM * 64 + (lane >> 2);   // + mi*16 + p*8
    long long colg = c0 + ucol;
#pragma unroll
    for (int mi = 0; mi < 4; ++mi) {
#pragma unroll
        for (int p = 0; p < 2; ++p) {       // p=0 -> elems 0,1; p=1 -> elems 2,3
            int row = row0 + mi * 16 + p * 8;
            long long off = (long long)row * H + colg;
            float2 cv = *reinterpret_cast<const float2*>(cell + off);
            float outS[2], outC[2];
#pragma unroll
            for (int e = 0; e < 2; ++e) {
                float gi = acc[mi][0][0][p * 2 + e] + bi[e];
                float gj = acc[mi][0][1][p * 2 + e] + bj[e];
                float gf = acc[mi][1][0][p * 2 + e] + bf[e];
                float go = acc[mi][1][1][p * 2 + e] + bo[e];
                float iv = ftanh(gi);
                float jv = fsigm(gj);
                float fv = fsigm(gf);
                float ov = ftanh(go);
                float cdv = (e ? cv.y : cv.x) * fv + iv * jv;
                outC[e] = cdv;
                outS[e] = ftanh(cdv) * ov;
            }
            *reinterpret_cast<float2*>(out + off) = make_float2(outS[0], outS[1]);
            *reinterpret_cast<float2*>(out + (long long)BATCH * H + off) =
                make_float2(outC[0], outC[1]);
        }
    }
}

// ===================== launch =====================
extern "C" void kernel_launch(void* const* d_in, const int* in_sizes, int n_in,
                              void* d_out, int out_size) {
    (void)in_sizes; (void)n_in; (void)out_size;
    const float* x     = (const float*)d_in[0];
    const float* state = (const float*)d_in[1];
    const float* cell  = (const float*)d_in[2];
    const float* Wx    = (const float*)d_in[3];
    const float* bx    = (const float*)d_in[4];
    const float* Wh    = (const float*)d_in[5];
    const float* bh    = (const float*)d_in[6];
    float* out = (float*)d_out;

    conv_aw<<<NA_BLOCKS + NW_X * NW_Y, 256>>>(x, state, Wx, Wh);

    cudaFuncSetAttribute(lstm_fused, cudaFuncAttributeMaxDynamicSharedMemorySize, SMEM_DYN);
    lstm_fused<<<dim3(H / GC, BATCH / BM), NTHREADS, SMEM_DYN>>>(cell, bx, bh, out);
}

// round 14
// speedup vs baseline: 1.1370x; 1.1370x over previous
#include <cuda_runtime.h>
#include <cuda_fp16.h>
#include <cstdint>

// ===================== problem dims =====================
static constexpr int BATCH = 16384;
static constexpr int H     = 1024;
static constexpr int KTOT  = 2048;    // IN + H
static constexpr int N4    = 4096;    // 4 gates * H

// ===================== tiling =====================
static constexpr int BM = 128;        // batch rows per CTA
static constexpr int BN = 128;        // C cols per CTA = 32 cols x 4 gates (gate-interleaved)
static constexpr int GC = 32;         // gate-cols per CTA
static constexpr int KC = 64;         // K halves per stage (128B rows)
static constexpr int NCHUNK = KTOT / KC;   // 32
static constexpr int STAGES = 3;
static constexpr int NTHREADS = 256;  // 8 warps; 2 CTAs/SM -> 16 warps/SM
static constexpr int A_BYTES = BM * KC * 2;          // 16 KB
static constexpr int B_BYTES = BN * KC * 2;          // 16 KB
static constexpr int STAGE_BYTES = A_BYTES + B_BYTES;// 32 KB
static constexpr int SMEM_DYN = STAGES * STAGE_BYTES; // 98304

// fp16 scratch (device globals: allocation-free)
__device__ __half g_A16[(long long)BATCH * KTOT];   // 64 MB
__device__ __half g_Wt16[(long long)N4 * KTOT];     // 16 MB, [n][k] K-major

// ===================== helpers =====================
__device__ __forceinline__ uint32_t smem_u32(const void* p) {
    uint32_t a;
    asm("{ .reg .u64 t; cvta.to.shared.u64 t, %1; cvt.u32.u64 %0, t; }" : "=r"(a) : "l"(p));
    return a;
}
__device__ __forceinline__ void cp_async16(uint32_t dst, const void* src) {
    asm volatile("cp.async.cg.shared.global [%0], [%1], 16;" :: "r"(dst), "l"(src));
}
__device__ __forceinline__ void ldsm_x4(uint32_t& r0, uint32_t& r1, uint32_t& r2, uint32_t& r3,
                                        uint32_t addr) {
    asm volatile("ldmatrix.sync.aligned.m8n8.x4.shared.b16 {%0,%1,%2,%3}, [%4];"
                 : "=r"(r0), "=r"(r1), "=r"(r2), "=r"(r3) : "r"(addr));
}
__device__ __forceinline__ void mma16816(float& d0, float& d1, float& d2, float& d3,
                                         uint32_t a0, uint32_t a1, uint32_t a2, uint32_t a3,
                                         uint32_t b0, uint32_t b1) {
    asm volatile("mma.sync.aligned.m16n8k16.row.col.f32.f16.f16.f32 "
                 "{%0,%1,%2,%3}, {%4,%5,%6,%7}, {%8,%9}, {%0,%1,%2,%3};"
                 : "+f"(d0), "+f"(d1), "+f"(d2), "+f"(d3)
                 : "r"(a0), "r"(a1), "r"(a2), "r"(a3), "r"(b0), "r"(b1));
}
__device__ __forceinline__ float ldg_cs(const float* p) {
    float v;
    asm volatile("ld.global.cs.f32 %0, [%1];" : "=f"(v) : "l"(p));
    return v;
}
__device__ __forceinline__ float2 ldg_cs2(const float* p) {
    float2 v;
    asm volatile("ld.global.cs.v2.f32 {%0,%1}, [%2];" : "=f"(v.x), "=f"(v.y) : "l"(p));
    return v;
}
__device__ __forceinline__ void stg_cs2(float* p, float2 v) {
    asm volatile("st.global.cs.v2.f32 [%0], {%1,%2};" :: "l"(p), "f"(v.x), "f"(v.y) : "memory");
}
__device__ __forceinline__ float fsigm(float v) { return 1.0f / (1.0f + __expf(-v)); }
__device__ __forceinline__ float ftanh(float v) { return 2.0f / (1.0f + __expf(-2.0f * v)) - 1.0f; }

// ===================== merged prologue =====================
// blocks [0, NA): convert A to fp16.  blocks [NA, NA+NW): transpose+convert W.
static constexpr int NA_BLOCKS = (int)(((long long)BATCH * KTOT / 8) / 256);  // 16384
static constexpr int NW_X = N4 / 32;   // 128
static constexpr int NW_Y = KTOT / 32; // 64

__global__ __launch_bounds__(256) void conv_aw(const float* __restrict__ x,
                                               const float* __restrict__ state,
                                               const float* __restrict__ Wx,
                                               const float* __restrict__ Wh) {
    int bid = blockIdx.x;
    if (bid < NA_BLOCKS) {
        long long idx8 = ((long long)bid * 256 + threadIdx.x) * 8;
        int b = (int)(idx8 >> 11);
        int k = (int)(idx8 & 2047);
        const float* src = (k < H) ? (x + (long long)b * H + k)
                                   : (state + (long long)b * H + (k - H));
        float4 f0 = *reinterpret_cast<const float4*>(src);
        float4 f1 = *reinterpret_cast<const float4*>(src + 4);
        __half2 h[4];
        h[0] = __floats2half2_rn(f0.x, f0.y);
        h[1] = __floats2half2_rn(f0.z, f0.w);
        h[2] = __floats2half2_rn(f1.x, f1.y);
        h[3] = __floats2half2_rn(f1.z, f1.w);
        *reinterpret_cast<uint4*>(&g_A16[idx8]) = *reinterpret_cast<uint4*>(h);
    } else {
        __shared__ float tile[32][33];
        int wb = bid - NA_BLOCKS;
        int n0 = (wb % NW_X) * 32;
        int k0 = (wb / NW_X) * 32;
        int tx = threadIdx.x & 31, ty = threadIdx.x >> 5;   // ty 0..7
#pragma unroll
        for (int i = 0; i < 32; i += 8) {
            int k = k0 + ty + i;
            const float* src = (k < H) ? (Wx + (long long)k * N4) : (Wh + (long long)(k - H) * N4);
            tile[ty + i][tx] = src[n0 + tx];
        }
        __syncthreads();
#pragma unroll
        for (int i = 0; i < 32; i += 8) {
            g_Wt16[(long long)(n0 + ty + i) * KTOT + k0 + tx] = __float2half_rn(tile[tx][ty + i]);
        }
    }
}

// ===================== fused LSTM GEMM + gates =====================
// B smem layout (gate-interleaved, BN=128 rows of 64 halves):
//   row r: warpN=r>>5, gate=(r>>3)&3, i=r&7  ->  n = gate*H + c0 + warpN*8 + i
// Warp tile N=32: nb in {0,1} n16 blocks; gate = nb*2 + h2.
__global__ __launch_bounds__(NTHREADS, 2) void lstm_fused(
    const float* __restrict__ cell, const float* __restrict__ bx,
    const float* __restrict__ bh, float* __restrict__ out)
{
    extern __shared__ char smem_raw[];
    __shared__ float bsum[BN];   // [gate][32] bias for this CTA's gate-col chunk

    const uint32_t sbase = smem_u32(smem_raw);
    int tid = threadIdx.x;
    int lane = tid & 31, wid = tid >> 5;
    int warpM = wid >> 2;            // 0..1, 64 rows each
    int warpN = wid & 3;             // 0..3, 8 gate-cols each (x4 gates)
    int m0 = blockIdx.y * BM;
    int c0 = blockIdx.x * GC;

    if (tid < BN) {   // bsum[g*32 + u] = bx[g*H + c0+u] + bh[g*H + c0+u]
        int g = tid >> 5, u = tid & 31;
        bsum[tid] = bx[g * H + c0 + u] + bh[g * H + c0 + u];
    }

    // --------- stage loader halves (split to smooth LSU pressure) ---------
    auto load_A_half = [&](int stage, int c) {
        uint32_t sA = sbase + stage * STAGE_BYTES;
        const __half* srcA = g_A16 + (long long)m0 * KTOT + c * KC;
#pragma unroll
        for (int i = 0; i < 4; ++i) {           // A: 1024 segs of 16B
            int idx = tid + i * NTHREADS;
            int row = idx >> 3, seg = idx & 7;
            cp_async16(sA + row * 128 + ((seg ^ (row & 7)) * 16),
                       srcA + (long long)row * KTOT + seg * 8);
        }
    };
    auto load_B_half = [&](int stage, int c) {
        uint32_t sB = sbase + stage * STAGE_BYTES + A_BYTES;
        const __half* srcB = g_Wt16 + c * KC;
#pragma unroll
        for (int i = 0; i < 4; ++i) {           // B: 1024 segs
            int idx = tid + i * NTHREADS;
            int r = idx >> 3, seg = idx & 7;
            int gate = (r >> 3) & 3;
            int colc = ((r >> 5) << 3) | (r & 7);
            int n = gate * H + c0 + colc;
            cp_async16(sB + r * 128 + ((seg ^ (r & 7)) * 16),
                       srcB + (long long)n * KTOT + seg * 8);
        }
    };
    auto commit = [&]() { asm volatile("cp.async.commit_group;" ::: "memory"); };

    // prologue loads: stages 0..STAGES-2
    load_A_half(0, 0); load_B_half(0, 0); commit();
    load_A_half(1, 1); load_B_half(1, 1); commit();

    float acc[4][2][2][4];   // [mi][nb][h2][4]; gate = nb*2 + h2
#pragma unroll
    for (int mi = 0; mi < 4; ++mi)
#pragma unroll
        for (int nb = 0; nb < 2; ++nb)
#pragma unroll
            for (int h2 = 0; h2 < 2; ++h2)
#pragma unroll
                for (int e = 0; e < 4; ++e) acc[mi][nb][h2][e] = 0.0f;

    // lane-fixed address components
    int rowA = warpM * 64 + (lane & 15);              // + mi*16
    int kslA = (lane >> 4);                           // 0/1 -> +8 halves
    int nB   = warpN * 32 + ((lane >> 4) & 1) * 8 + (lane & 7);   // + nb*16
    int kslB = (lane >> 3) & 1;

    auto compute_ks = [&](uint32_t sA, uint32_t sB, int ks) {
        uint32_t a[4][4];
#pragma unroll
        for (int mi = 0; mi < 4; ++mi) {
            int row = rowA + mi * 16;
            int seg = (ks * 2 + kslA) ^ (row & 7);
            ldsm_x4(a[mi][0], a[mi][1], a[mi][2], a[mi][3], sA + row * 128 + seg * 16);
        }
        uint32_t b[2][4];
#pragma unroll
        for (int nb = 0; nb < 2; ++nb) {
            int n = nB + nb * 16;
            int seg = (ks * 2 + kslB) ^ (n & 7);
            ldsm_x4(b[nb][0], b[nb][1], b[nb][2], b[nb][3], sB + n * 128 + seg * 16);
        }
#pragma unroll
        for (int mi = 0; mi < 4; ++mi)
#pragma unroll
            for (int nb = 0; nb < 2; ++nb) {
                mma16816(acc[mi][nb][0][0], acc[mi][nb][0][1], acc[mi][nb][0][2], acc[mi][nb][0][3],
                         a[mi][0], a[mi][1], a[mi][2], a[mi][3], b[nb][0], b[nb][1]);
                mma16816(acc[mi][nb][1][0], acc[mi][nb][1][1], acc[mi][nb][1][2], acc[mi][nb][1][3],
                         a[mi][0], a[mi][1], a[mi][2], a[mi][3], b[nb][2], b[nb][3]);
            }
    };

#pragma unroll 1
    for (int c = 0; c < NCHUNK; ++c) {
        // per-thread: chunk-c copies landed (2 groups pending here: c, c+1)
        asm volatile("cp.async.wait_group %0;" :: "n"(STAGES - 2) : "memory");
        // CTA-wide: everyone's chunk-c copies landed; also all chunk c-1 reads
        // are done, so stage (c+2)%3 = (c-1)%3 is free for the loads below.
        __syncthreads();

        uint32_t sA = sbase + (c % STAGES) * STAGE_BYTES;
        uint32_t sB = sA + A_BYTES;
        int cp = c + STAGES - 1;
        bool do_load = (cp < NCHUNK);
        int sp = cp % STAGES;

        // ks=0 first: tensor work starts immediately after the barrier; the
        // next-stage cp.async burst is split across ks slices to avoid a
        // single LSU hog blocking the LDSM streams.
        compute_ks(sA, sB, 0);
        if (do_load) load_A_half(sp, cp);
        compute_ks(sA, sB, 1);
        if (do_load) load_B_half(sp, cp);
        compute_ks(sA, sB, 2);
        commit();   // exactly one group per iteration (empty in drain)
        compute_ks(sA, sB, 3);
    }

    // --------- register-direct fused gate epilogue ---------
    // gate g = nb*2+h2: gi=(0,0), gj=(0,1), gf=(1,0), go=(1,1)
    int ucol = warpN * 8 + (lane & 3) * 2;
    float bi[2], bj[2], bf[2], bo[2];
#pragma unroll
    for (int e = 0; e < 2; ++e) {
        int u = ucol + e;
        bi[e] = bsum[0  + u];
        bj[e] = bsum[32 + u];
        bf[e] = bsum[64 + u];
        bo[e] = bsum[96 + u];
    }

    int row0 = m0 + warpM * 64 + (lane >> 2);   // + mi*16 + p*8
    long long colg = c0 + ucol;
#pragma unroll
    for (int mi = 0; mi < 4; ++mi) {
#pragma unroll
        for (int p = 0; p < 2; ++p) {       // p=0 -> elems 0,1; p=1 -> elems 2,3
            int row = row0 + mi * 16 + p * 8;
            long long off = (long long)row * H + colg;
            float2 cv = ldg_cs2(cell + off);
            float outS[2], outC[2];
#pragma unroll
            for (int e = 0; e < 2; ++e) {
                float gi = acc[mi][0][0][p * 2 + e] + bi[e];
                float gj = acc[mi][0][1][p * 2 + e] + bj[e];
                float gf = acc[mi][1][0][p * 2 + e] + bf[e];
                float go = acc[mi][1][1][p * 2 + e] + bo[e];
                float iv = ftanh(gi);
                float jv = fsigm(gj);
                float fv = fsigm(gf);
                float ov = ftanh(go);
                float cdv = (e ? cv.y : cv.x) * fv + iv * jv;
                outC[e] = cdv;
                outS[e] = ftanh(cdv) * ov;
            }
            stg_cs2(out + off, make_float2(outS[0], outS[1]));
            stg_cs2(out + (long long)BATCH * H + off, make_float2(outC[0], outC[1]));
        }
    }
}

// ===================== launch =====================
extern "C" void kernel_launch(void* const* d_in, const int* in_sizes, int n_in,
                              void* d_out, int out_size) {
    (void)in_sizes; (void)n_in; (void)out_size;
    const float* x     = (const float*)d_in[0];
    const float* state = (const float*)d_in[1];
    const float* cell  = (const float*)d_in[2];
    const float* Wx    = (const float*)d_in[3];
    const float* bx    = (const float*)d_in[4];
    const float* Wh    = (const float*)d_in[5];
    const float* bh    = (const float*)d_in[6];
    float* out = (float*)d_out;

    conv_aw<<<NA_BLOCKS + NW_X * NW_Y, 256>>>(x, state, Wx, Wh);

    cudaFuncSetAttribute(lstm_fused, cudaFuncAttributeMaxDynamicSharedMemorySize, SMEM_DYN);
    lstm_fused<<<dim3(H / GC, BATCH / BM), NTHREADS, SMEM_DYN>>>(cell, bx, bh, out);
}

// round 15
// speedup vs baseline: 1.1971x; 1.0528x over previous
#include <cuda_runtime.h>
#include <cuda_fp16.h>
#include <cstdint>

// ===================== problem dims =====================
static constexpr int BATCH = 16384;
static constexpr int H     = 1024;
static constexpr int KTOT  = 2048;    // IN + H
static constexpr int N4    = 4096;    // 4 gates * H

// ===================== tiling =====================
static constexpr int BM = 128;        // batch rows per CTA
static constexpr int BN = 128;        // C cols per CTA = 32 cols x 4 gates (gate-interleaved)
static constexpr int GC = 32;         // gate-cols per CTA
static constexpr int KC = 64;         // K halves per stage (128B rows)
static constexpr int NCHUNK = KTOT / KC;   // 32
static constexpr int STAGES = 3;
static constexpr int NTHREADS = 256;  // 8 warps; 2 CTAs/SM -> 16 warps/SM
static constexpr int A_BYTES = BM * KC * 2;          // 16 KB
static constexpr int B_BYTES = BN * KC * 2;          // 16 KB
static constexpr int STAGE_BYTES = A_BYTES + B_BYTES;// 32 KB
static constexpr int SMEM_DYN = STAGES * STAGE_BYTES; // 98304

// fp16 scratch (device globals: allocation-free)
__device__ __half g_A16[(long long)BATCH * KTOT];   // 64 MB
__device__ __half g_Wt16[(long long)N4 * KTOT];     // 16 MB, [n][k] K-major

// ===================== helpers =====================
__device__ __forceinline__ uint32_t smem_u32(const void* p) {
    uint32_t a;
    asm("{ .reg .u64 t; cvta.to.shared.u64 t, %1; cvt.u32.u64 %0, t; }" : "=r"(a) : "l"(p));
    return a;
}
__device__ __forceinline__ void cp_async16(uint32_t dst, const void* src) {
    asm volatile("cp.async.cg.shared.global [%0], [%1], 16;" :: "r"(dst), "l"(src));
}
__device__ __forceinline__ void ldsm_x4(uint32_t& r0, uint32_t& r1, uint32_t& r2, uint32_t& r3,
                                        uint32_t addr) {
    asm volatile("ldmatrix.sync.aligned.m8n8.x4.shared.b16 {%0,%1,%2,%3}, [%4];"
                 : "=r"(r0), "=r"(r1), "=r"(r2), "=r"(r3) : "r"(addr));
}
__device__ __forceinline__ void mma16816(float& d0, float& d1, float& d2, float& d3,
                                         uint32_t a0, uint32_t a1, uint32_t a2, uint32_t a3,
                                         uint32_t b0, uint32_t b1) {
    asm volatile("mma.sync.aligned.m16n8k16.row.col.f32.f16.f16.f32 "
                 "{%0,%1,%2,%3}, {%4,%5,%6,%7}, {%8,%9}, {%0,%1,%2,%3};"
                 : "+f"(d0), "+f"(d1), "+f"(d2), "+f"(d3)
                 : "r"(a0), "r"(a1), "r"(a2), "r"(a3), "r"(b0), "r"(b1));
}
__device__ __forceinline__ float fsigm(float v) { return 1.0f / (1.0f + __expf(-v)); }
__device__ __forceinline__ float ftanh(float v) { return 2.0f / (1.0f + __expf(-2.0f * v)) - 1.0f; }

// ===================== merged prologue =====================
// blocks [0, NA): convert A to fp16.  blocks [NA, NA+NW): transpose+convert W.
static constexpr int NA_BLOCKS = (int)(((long long)BATCH * KTOT / 8) / 256);  // 16384
static constexpr int NW_X = N4 / 32;   // 128
static constexpr int NW_Y = KTOT / 32; // 64

__global__ __launch_bounds__(256) void conv_aw(const float* __restrict__ x,
                                               const float* __restrict__ state,
                                               const float* __restrict__ Wx,
                                               const float* __restrict__ Wh) {
    int bid = blockIdx.x;
    if (bid < NA_BLOCKS) {
        long long idx8 = ((long long)bid * 256 + threadIdx.x) * 8;
        int b = (int)(idx8 >> 11);
        int k = (int)(idx8 & 2047);
        const float* src = (k < H) ? (x + (long long)b * H + k)
                                   : (state + (long long)b * H + (k - H));
        float4 f0 = *reinterpret_cast<const float4*>(src);
        float4 f1 = *reinterpret_cast<const float4*>(src + 4);
        __half2 h[4];
        h[0] = __floats2half2_rn(f0.x, f0.y);
        h[1] = __floats2half2_rn(f0.z, f0.w);
        h[2] = __floats2half2_rn(f1.x, f1.y);
        h[3] = __floats2half2_rn(f1.z, f1.w);
        *reinterpret_cast<uint4*>(&g_A16[idx8]) = *reinterpret_cast<uint4*>(h);
    } else {
        __shared__ float tile[32][33];
        int wb = bid - NA_BLOCKS;
        int n0 = (wb % NW_X) * 32;
        int k0 = (wb / NW_X) * 32;
        int tx = threadIdx.x & 31, ty = threadIdx.x >> 5;   // ty 0..7
#pragma unroll
        for (int i = 0; i < 32; i += 8) {
            int k = k0 + ty + i;
            const float* src = (k < H) ? (Wx + (long long)k * N4) : (Wh + (long long)(k - H) * N4);
            tile[ty + i][tx] = src[n0 + tx];
        }
        __syncthreads();
#pragma unroll
        for (int i = 0; i < 32; i += 8) {
            g_Wt16[(long long)(n0 + ty + i) * KTOT + k0 + tx] = __float2half_rn(tile[tx][ty + i]);
        }
    }
}

// ===================== fused LSTM GEMM + gates =====================
// B smem layout (gate-interleaved, BN=128 rows of 64 halves):
//   row r: warpN=r>>5, gate=(r>>3)&3, i=r&7  ->  n = gate*H + c0 + warpN*8 + i
// Warp tile N=32: nb in {0,1} n16 blocks; gate = nb*2 + h2.
__global__ __launch_bounds__(NTHREADS, 2) void lstm_fused(
    const float* __restrict__ cell, const float* __restrict__ bx,
    const float* __restrict__ bh, float* __restrict__ out)
{
    extern __shared__ char smem_raw[];
    __shared__ float bsum[BN];   // [gate][32] bias for this CTA's gate-col chunk

    const uint32_t sbase = smem_u32(smem_raw);
    int tid = threadIdx.x;
    int lane = tid & 31, wid = tid >> 5;
    int warpM = wid >> 2;            // 0..1, 64 rows each
    int warpN = wid & 3;             // 0..3, 8 gate-cols each (x4 gates)
    int m0 = blockIdx.y * BM;
    int c0 = blockIdx.x * GC;

    if (tid < BN) {   // bsum[g*32 + u] = bx[g*H + c0+u] + bh[g*H + c0+u]
        int g = tid >> 5, u = tid & 31;
        bsum[tid] = bx[g * H + c0 + u] + bh[g * H + c0 + u];
    }

    // --------- stage loader (256 threads) ---------
    auto load_stage = [&](int stage, int c) {
        uint32_t sA = sbase + stage * STAGE_BYTES;
        uint32_t sB = sA + A_BYTES;
        const __half* srcA = g_A16 + (long long)m0 * KTOT + c * KC;
        const __half* srcB = g_Wt16 + c * KC;
#pragma unroll
        for (int i = 0; i < 4; ++i) {           // A: 1024 segs of 16B
            int idx = tid + i * NTHREADS;
            int row = idx >> 3, seg = idx & 7;
            cp_async16(sA + row * 128 + ((seg ^ (row & 7)) * 16),
                       srcA + (long long)row * KTOT + seg * 8);
        }
#pragma unroll
        for (int i = 0; i < 4; ++i) {           // B: 1024 segs
            int idx = tid + i * NTHREADS;
            int r = idx >> 3, seg = idx & 7;
            int gate = (r >> 3) & 3;
            int colc = ((r >> 5) << 3) | (r & 7);
            int n = gate * H + c0 + colc;
            cp_async16(sB + r * 128 + ((seg ^ (r & 7)) * 16),
                       srcB + (long long)n * KTOT + seg * 8);
        }
        asm volatile("cp.async.commit_group;" ::: "memory");
    };

    // prologue loads: stages 0..STAGES-2
    load_stage(0, 0);
    load_stage(1, 1);

    float acc[4][2][2][4];   // [mi][nb][h2][4]; gate = nb*2 + h2
#pragma unroll
    for (int mi = 0; mi < 4; ++mi)
#pragma unroll
        for (int nb = 0; nb < 2; ++nb)
#pragma unroll
            for (int h2 = 0; h2 < 2; ++h2)
#pragma unroll
                for (int e = 0; e < 4; ++e) acc[mi][nb][h2][e] = 0.0f;

    // lane-fixed address components
    int rowA = warpM * 64 + (lane & 15);              // + mi*16
    int kslA = (lane >> 4);                           // 0/1 -> +8 halves
    int nB   = warpN * 32 + ((lane >> 4) & 1) * 8 + (lane & 7);   // + nb*16
    int kslB = (lane >> 3) & 1;

    // one ks-slice of compute: LDSM fragments + 8 HMMA
    auto compute_ks = [&](uint32_t sA, uint32_t sB, int ks) {
        uint32_t a[4][4];
#pragma unroll
        for (int mi = 0; mi < 4; ++mi) {
            int row = rowA + mi * 16;
            int seg = (ks * 2 + kslA) ^ (row & 7);
            ldsm_x4(a[mi][0], a[mi][1], a[mi][2], a[mi][3], sA + row * 128 + seg * 16);
        }
        uint32_t b[2][4];
#pragma unroll
        for (int nb = 0; nb < 2; ++nb) {
            int n = nB + nb * 16;
            int seg = (ks * 2 + kslB) ^ (n & 7);
            ldsm_x4(b[nb][0], b[nb][1], b[nb][2], b[nb][3], sB + n * 128 + seg * 16);
        }
#pragma unroll
        for (int mi = 0; mi < 4; ++mi)
#pragma unroll
            for (int nb = 0; nb < 2; ++nb) {
                mma16816(acc[mi][nb][0][0], acc[mi][nb][0][1], acc[mi][nb][0][2], acc[mi][nb][0][3],
                         a[mi][0], a[mi][1], a[mi][2], a[mi][3], b[nb][0], b[nb][1]);
                mma16816(acc[mi][nb][1][0], acc[mi][nb][1][1], acc[mi][nb][1][2], acc[mi][nb][1][3],
                         a[mi][0], a[mi][1], a[mi][2], a[mi][3], b[nb][2], b[nb][3]);
            }
    };

#pragma unroll 1
    for (int c = 0; c < NCHUNK; ++c) {
        // per-thread: chunk-c copies landed (2 groups pending here: c, c+1)
        asm volatile("cp.async.wait_group %0;" :: "n"(STAGES - 2) : "memory");
        // CTA-wide: everyone's chunk-c copies landed; also all chunk c-1 reads
        // are done, so stage (c+2)%3 = (c-1)%3 is free for the loads below.
        __syncthreads();

        uint32_t sA = sbase + (c % STAGES) * STAGE_BYTES;
        uint32_t sB = sA + A_BYTES;

        // ks=0 first: get LDSM+HMMA flowing immediately after the barrier...
        compute_ks(sA, sB, 0);
        // ...then issue the next-stage cp.async burst, overlapped with ks=1..3
        if (c + STAGES - 1 < NCHUNK) load_stage((c + STAGES - 1) % STAGES, c + STAGES - 1);
        else asm volatile("cp.async.commit_group;" ::: "memory");
        compute_ks(sA, sB, 1);
        compute_ks(sA, sB, 2);
        compute_ks(sA, sB, 3);
    }

    // --------- register-direct fused gate epilogue ---------
    // gate g = nb*2+h2: gi=(0,0), gj=(0,1), gf=(1,0), go=(1,1)
    int ucol = warpN * 8 + (lane & 3) * 2;
    float bi[2], bj[2], bf[2], bo[2];
#pragma unroll
    for (int e = 0; e < 2; ++e) {
        int u = ucol + e;
        bi[e] = bsum[0  + u];
        bj[e] = bsum[32 + u];
        bf[e] = bsum[64 + u];
        bo[e] = bsum[96 + u];
    }

    int row0 = m0 + warpM * 64 + (lane >> 2);   // + mi*16 + p*8
    long long colg = c0 + ucol;
#pragma unroll
    for (int mi = 0; mi < 4; ++mi) {
#pragma unroll
        for (int p = 0; p < 2; ++p) {       // p=0 -> elems 0,1; p=1 -> elems 2,3
            int row = row0 + mi * 16 + p * 8;
            long long off = (long long)row * H + colg;
            float2 cv = *reinterpret_cast<const float2*>(cell + off);
            float outS[2], outC[2];
#pragma unroll
            for (int e = 0; e < 2; ++e) {
                float gi = acc[mi][0][0][p * 2 + e] + bi[e];
                float gj = acc[mi][0][1][p * 2 + e] + bj[e];
                float gf = acc[mi][1][0][p * 2 + e] + bf[e];
                float go = acc[mi][1][1][p * 2 + e] + bo[e];
                float iv = ftanh(gi);
                float jv = fsigm(gj);
                float fv = fsigm(gf);
                float ov = ftanh(go);
                float cdv = (e ? cv.y : cv.x) * fv + iv * jv;
                outC[e] = cdv;
                outS[e] = ftanh(cdv) * ov;
            }
            *reinterpret_cast<float2*>(out + off) = make_float2(outS[0], outS[1]);
            *reinterpret_cast<float2*>(out + (long long)BATCH * H + off) =
                make_float2(outC[0], outC[1]);
        }
    }
}

// ===================== launch =====================
extern "C" void kernel_launch(void* const* d_in, const int* in_sizes, int n_in,
                              void* d_out, int out_size) {
    (void)in_sizes; (void)n_in; (void)out_size;
    const float* x     = (const float*)d_in[0];
    const float* state = (const float*)d_in[1];
    const float* cell  = (const float*)d_in[2];
    const float* Wx    = (const float*)d_in[3];
    const float* bx    = (const float*)d_in[4];
    const float* Wh    = (const float*)d_in[5];
    const float* bh    = (const float*)d_in[6];
    float* out = (float*)d_out;

    conv_aw<<<NA_BLOCKS + NW_X * NW_Y, 256>>>(x, state, Wx, Wh);

    cudaFuncSetAttribute(lstm_fused, cudaFuncAttributeMaxDynamicSharedMemorySize, SMEM_DYN);
    lstm_fused<<<dim3(H / GC, BATCH / BM), NTHREADS, SMEM_DYN>>>(cell, bx, bh, out);
}

// round 16
// speedup vs baseline: 1.2152x; 1.0151x over previous
#include <cuda_runtime.h>
#include <cuda_fp16.h>
#include <cstdint>

// ===================== problem dims =====================
static constexpr int BATCH = 16384;
static constexpr int H     = 1024;
static constexpr int KTOT  = 2048;    // IN + H
static constexpr int N4    = 4096;    // 4 gates * H

// ===================== tiling =====================
static constexpr int BM = 128;        // batch rows per CTA
static constexpr int BN = 128;        // C cols per CTA = 32 cols x 4 gates (gate-interleaved)
static constexpr int GC = 32;         // gate-cols per CTA
static constexpr int KC = 64;         // K halves per stage (128B rows)
static constexpr int NCHUNK = KTOT / KC;   // 32
static constexpr int STAGES = 3;
static constexpr int NTHREADS = 256;  // 8 warps; 2 CTAs/SM -> 16 warps/SM
static constexpr int A_BYTES = BM * KC * 2;          // 16 KB
static constexpr int B_BYTES = BN * KC * 2;          // 16 KB
static constexpr int STAGE_BYTES = A_BYTES + B_BYTES;// 32 KB
static constexpr int SMEM_DYN = STAGES * STAGE_BYTES; // 98304

// fp16 scratch (device globals: allocation-free)
__device__ __half g_A16[(long long)BATCH * KTOT];   // 64 MB
__device__ __half g_Wt16[(long long)N4 * KTOT];     // 16 MB, [n][k] K-major

// ===================== helpers =====================
__device__ __forceinline__ uint32_t smem_u32(const void* p) {
    uint32_t a;
    asm("{ .reg .u64 t; cvta.to.shared.u64 t, %1; cvt.u32.u64 %0, t; }" : "=r"(a) : "l"(p));
    return a;
}
__device__ __forceinline__ void cp_async16(uint32_t dst, const void* src) {
    asm volatile("cp.async.cg.shared.global [%0], [%1], 16;" :: "r"(dst), "l"(src));
}
__device__ __forceinline__ void ldsm_x4(uint32_t& r0, uint32_t& r1, uint32_t& r2, uint32_t& r3,
                                        uint32_t addr) {
    asm volatile("ldmatrix.sync.aligned.m8n8.x4.shared.b16 {%0,%1,%2,%3}, [%4];"
                 : "=r"(r0), "=r"(r1), "=r"(r2), "=r"(r3) : "r"(addr));
}
__device__ __forceinline__ void mma16816(float& d0, float& d1, float& d2, float& d3,
                                         uint32_t a0, uint32_t a1, uint32_t a2, uint32_t a3,
                                         uint32_t b0, uint32_t b1) {
    asm volatile("mma.sync.aligned.m16n8k16.row.col.f32.f16.f16.f32 "
                 "{%0,%1,%2,%3}, {%4,%5,%6,%7}, {%8,%9}, {%0,%1,%2,%3};"
                 : "+f"(d0), "+f"(d1), "+f"(d2), "+f"(d3)
                 : "r"(a0), "r"(a1), "r"(a2), "r"(a3), "r"(b0), "r"(b1));
}
__device__ __forceinline__ float fsigm(float v) { return 1.0f / (1.0f + __expf(-v)); }
__device__ __forceinline__ float ftanh(float v) { return 2.0f / (1.0f + __expf(-2.0f * v)) - 1.0f; }

// ===================== merged prologue =====================
// blocks [0, NA): convert A to fp16.  blocks [NA, NA+NW): transpose+convert W.
static constexpr int NA_BLOCKS = (int)(((long long)BATCH * KTOT / 8) / 256);  // 16384
static constexpr int NW_X = N4 / 32;   // 128
static constexpr int NW_Y = KTOT / 32; // 64

__global__ __launch_bounds__(256) void conv_aw(const float* __restrict__ x,
                                               const float* __restrict__ state,
                                               const float* __restrict__ Wx,
                                               const float* __restrict__ Wh) {
    int bid = blockIdx.x;
    if (bid < NA_BLOCKS) {
        long long idx8 = ((long long)bid * 256 + threadIdx.x) * 8;
        int b = (int)(idx8 >> 11);
        int k = (int)(idx8 & 2047);
        const float* src = (k < H) ? (x + (long long)b * H + k)
                                   : (state + (long long)b * H + (k - H));
        float4 f0 = *reinterpret_cast<const float4*>(src);
        float4 f1 = *reinterpret_cast<const float4*>(src + 4);
        __half2 h[4];
        h[0] = __floats2half2_rn(f0.x, f0.y);
        h[1] = __floats2half2_rn(f0.z, f0.w);
        h[2] = __floats2half2_rn(f1.x, f1.y);
        h[3] = __floats2half2_rn(f1.z, f1.w);
        *reinterpret_cast<uint4*>(&g_A16[idx8]) = *reinterpret_cast<uint4*>(h);
    } else {
        __shared__ float tile[32][33];
        int wb = bid - NA_BLOCKS;
        int n0 = (wb % NW_X) * 32;
        int k0 = (wb / NW_X) * 32;
        int tx = threadIdx.x & 31, ty = threadIdx.x >> 5;   // ty 0..7
#pragma unroll
        for (int i = 0; i < 32; i += 8) {
            int k = k0 + ty + i;
            const float* src = (k < H) ? (Wx + (long long)k * N4) : (Wh + (long long)(k - H) * N4);
            tile[ty + i][tx] = src[n0 + tx];
        }
        __syncthreads();
#pragma unroll
        for (int i = 0; i < 32; i += 8) {
            g_Wt16[(long long)(n0 + ty + i) * KTOT + k0 + tx] = __float2half_rn(tile[tx][ty + i]);
        }
    }
}

// ===================== fused LSTM GEMM + gates =====================
// B smem layout (gate-interleaved, BN=128 rows of 64 halves):
//   row r: warpN=r>>5, gate=(r>>3)&3, i=r&7  ->  n = gate*H + c0 + warpN*8 + i
// Warp tile N=32: nb in {0,1} n16 blocks; gate = nb*2 + h2.
// Pipeline (per chunk): bar.sync -> ks0 -> load(c+2)+commit -> wait_group(1)
// [retires chunk c+1 for the NEXT iteration, off the barrier critical path]
// -> ks1..ks3.  Barrier release implies all threads' chunk-c data landed,
// because every thread's wait for chunk c executed before its barrier arrival.
__global__ __launch_bounds__(NTHREADS, 2) void lstm_fused(
    const float* __restrict__ cell, const float* __restrict__ bx,
    const float* __restrict__ bh, float* __restrict__ out)
{
    extern __shared__ char smem_raw[];
    __shared__ float bsum[BN];   // [gate][32] bias for this CTA's gate-col chunk

    const uint32_t sbase = smem_u32(smem_raw);
    int tid = threadIdx.x;
    int lane = tid & 31, wid = tid >> 5;
    int warpM = wid >> 2;            // 0..1, 64 rows each
    int warpN = wid & 3;             // 0..3, 8 gate-cols each (x4 gates)
    int m0 = blockIdx.y * BM;
    int c0 = blockIdx.x * GC;

    if (tid < BN) {   // bsum[g*32 + u] = bx[g*H + c0+u] + bh[g*H + c0+u]
        int g = tid >> 5, u = tid & 31;
        bsum[tid] = bx[g * H + c0 + u] + bh[g * H + c0 + u];
    }

    // --------- stage loader (256 threads) ---------
    auto load_stage = [&](int stage, int c) {
        uint32_t sA = sbase + stage * STAGE_BYTES;
        uint32_t sB = sA + A_BYTES;
        const __half* srcA = g_A16 + (long long)m0 * KTOT + c * KC;
        const __half* srcB = g_Wt16 + c * KC;
#pragma unroll
        for (int i = 0; i < 4; ++i) {           // A: 1024 segs of 16B
            int idx = tid + i * NTHREADS;
            int row = idx >> 3, seg = idx & 7;
            cp_async16(sA + row * 128 + ((seg ^ (row & 7)) * 16),
                       srcA + (long long)row * KTOT + seg * 8);
        }
#pragma unroll
        for (int i = 0; i < 4; ++i) {           // B: 1024 segs
            int idx = tid + i * NTHREADS;
            int r = idx >> 3, seg = idx & 7;
            int gate = (r >> 3) & 3;
            int colc = ((r >> 5) << 3) | (r & 7);
            int n = gate * H + c0 + colc;
            cp_async16(sB + r * 128 + ((seg ^ (r & 7)) * 16),
                       srcB + (long long)n * KTOT + seg * 8);
        }
        asm volatile("cp.async.commit_group;" ::: "memory");
    };

    // prologue loads: stages 0..STAGES-2, then retire chunk 0 early
    load_stage(0, 0);
    load_stage(1, 1);
    asm volatile("cp.async.wait_group %0;" :: "n"(STAGES - 2) : "memory");  // chunk 0 landed

    float acc[4][2][2][4];   // [mi][nb][h2][4]; gate = nb*2 + h2
#pragma unroll
    for (int mi = 0; mi < 4; ++mi)
#pragma unroll
        for (int nb = 0; nb < 2; ++nb)
#pragma unroll
            for (int h2 = 0; h2 < 2; ++h2)
#pragma unroll
                for (int e = 0; e < 4; ++e) acc[mi][nb][h2][e] = 0.0f;

    // lane-fixed address components
    int rowA = warpM * 64 + (lane & 15);              // + mi*16
    int kslA = (lane >> 4);                           // 0/1 -> +8 halves
    int nB   = warpN * 32 + ((lane >> 4) & 1) * 8 + (lane & 7);   // + nb*16
    int kslB = (lane >> 3) & 1;

    // one ks-slice of compute: LDSM fragments + 8 HMMA
    auto compute_ks = [&](uint32_t sA, uint32_t sB, int ks) {
        uint32_t a[4][4];
#pragma unroll
        for (int mi = 0; mi < 4; ++mi) {
            int row = rowA + mi * 16;
            int seg = (ks * 2 + kslA) ^ (row & 7);
            ldsm_x4(a[mi][0], a[mi][1], a[mi][2], a[mi][3], sA + row * 128 + seg * 16);
        }
        uint32_t b[2][4];
#pragma unroll
        for (int nb = 0; nb < 2; ++nb) {
            int n = nB + nb * 16;
            int seg = (ks * 2 + kslB) ^ (n & 7);
            ldsm_x4(b[nb][0], b[nb][1], b[nb][2], b[nb][3], sB + n * 128 + seg * 16);
        }
#pragma unroll
        for (int mi = 0; mi < 4; ++mi)
#pragma unroll
            for (int nb = 0; nb < 2; ++nb) {
                mma16816(acc[mi][nb][0][0], acc[mi][nb][0][1], acc[mi][nb][0][2], acc[mi][nb][0][3],
                         a[mi][0], a[mi][1], a[mi][2], a[mi][3], b[nb][0], b[nb][1]);
                mma16816(acc[mi][nb][1][0], acc[mi][nb][1][1], acc[mi][nb][1][2], acc[mi][nb][1][3],
                         a[mi][0], a[mi][1], a[mi][2], a[mi][3], b[nb][2], b[nb][3]);
            }
    };

#pragma unroll 1
    for (int c = 0; c < NCHUNK; ++c) {
        // CTA-wide rendezvous. Release implies:
        //  - every thread's chunk-c copies landed (its wait ran before arrival)
        //  - all chunk c-1 reads done -> stage (c+2)%3 free for the loads below
        __syncthreads();

        uint32_t sA = sbase + (c % STAGES) * STAGE_BYTES;
        uint32_t sB = sA + A_BYTES;

        // ks=0 first: LDSM+HMMA flow immediately out of the barrier...
        compute_ks(sA, sB, 0);
        // ...then issue next-stage cp.async burst, overlapped with ks=1..3
        if (c + STAGES - 1 < NCHUNK) load_stage((c + STAGES - 1) % STAGES, c + STAGES - 1);
        else asm volatile("cp.async.commit_group;" ::: "memory");
        // retire chunk c+1 NOW (mid-chunk, tensor work still queued behind it)
        // pending {c+1, c+2} -> {c+2}; next iteration's barrier needs no wait.
        asm volatile("cp.async.wait_group %0;" :: "n"(STAGES - 2) : "memory");
        compute_ks(sA, sB, 1);
        compute_ks(sA, sB, 2);
        compute_ks(sA, sB, 3);
    }

    // --------- register-direct fused gate epilogue ---------
    // gate g = nb*2+h2: gi=(0,0), gj=(0,1), gf=(1,0), go=(1,1)
    int ucol = warpN * 8 + (lane & 3) * 2;
    float bi[2], bj[2], bf[2], bo[2];
#pragma unroll
    for (int e = 0; e < 2; ++e) {
        int u = ucol + e;
        bi[e] = bsum[0  + u];
        bj[e] = bsum[32 + u];
        bf[e] = bsum[64 + u];
        bo[e] = bsum[96 + u];
    }

    int row0 = m0 + warpM * 64 + (lane >> 2);   // + mi*16 + p*8
    long long colg = c0 + ucol;
#pragma unroll
    for (int mi = 0; mi < 4; ++mi) {
#pragma unroll
        for (int p = 0; p < 2; ++p) {       // p=0 -> elems 0,1; p=1 -> elems 2,3
            int row = row0 + mi * 16 + p * 8;
            long long off = (long long)row * H + colg;
            float2 cv = *reinterpret_cast<const float2*>(cell + off);
            float outS[2], outC[2];
#pragma unroll
            for (int e = 0; e < 2; ++e) {
                float gi = acc[mi][0][0][p * 2 + e] + bi[e];
                float gj = acc[mi][0][1][p * 2 + e] + bj[e];
                float gf = acc[mi][1][0][p * 2 + e] + bf[e];
                float go = acc[mi][1][1][p * 2 + e] + bo[e];
                float iv = ftanh(gi);
                float jv = fsigm(gj);
                float fv = fsigm(gf);
                float ov = ftanh(go);
                float cdv = (e ? cv.y : cv.x) * fv + iv * jv;
                outC[e] = cdv;
                outS[e] = ftanh(cdv) * ov;
            }
            *reinterpret_cast<float2*>(out + off) = make_float2(outS[0], outS[1]);
            *reinterpret_cast<float2*>(out + (long long)BATCH * H + off) =
                make_float2(outC[0], outC[1]);
        }
    }
}

// ===================== launch =====================
extern "C" void kernel_launch(void* const* d_in, const int* in_sizes, int n_in,
                              void* d_out, int out_size) {
    (void)in_sizes; (void)n_in; (void)out_size;
    const float* x     = (const float*)d_in[0];
    const float* state = (const float*)d_in[1];
    const float* cell  = (const float*)d_in[2];
    const float* Wx    = (const float*)d_in[3];
    const float* bx    = (const float*)d_in[4];
    const float* Wh    = (const float*)d_in[5];
    const float* bh    = (const float*)d_in[6];
    float* out = (float*)d_out;

    conv_aw<<<NA_BLOCKS + NW_X * NW_Y, 256>>>(x, state, Wx, Wh);

    cudaFuncSetAttribute(lstm_fused, cudaFuncAttributeMaxDynamicSharedMemorySize, SMEM_DYN);
    lstm_fused<<<dim3(H / GC, BATCH / BM), NTHREADS, SMEM_DYN>>>(cell, bx, bh, out);
}

// round 17
// speedup vs baseline: 1.2887x; 1.0605x over previous
#include <cuda_runtime.h>
#include <cuda_fp16.h>
#include <cstdint>

// ===================== problem dims =====================
static constexpr int BATCH = 16384;
static constexpr int H     = 1024;
static constexpr int KTOT  = 2048;    // IN + H
static constexpr int N4    = 4096;    // 4 gates * H

// ===================== tiling =====================
static constexpr int BM = 128;        // batch rows per CTA
static constexpr int BN = 128;        // C cols per CTA = 32 cols x 4 gates (gate-interleaved)
static constexpr int GC = 32;         // gate-cols per CTA
static constexpr int KC = 64;         // K halves per stage (128B rows)
static constexpr int NCHUNK = KTOT / KC;   // 32
static constexpr int STAGES = 3;
static constexpr int NTHREADS = 256;  // 8 warps; 2 CTAs/SM -> 16 warps/SM
static constexpr int A_BYTES = BM * KC * 2;          // 16 KB
static constexpr int B_BYTES = BN * KC * 2;          // 16 KB
static constexpr int STAGE_BYTES = A_BYTES + B_BYTES;// 32 KB
static constexpr int SMEM_DYN = STAGES * STAGE_BYTES; // 98304

// fp16 scratch (device globals: allocation-free)
__device__ __half g_A16[(long long)BATCH * KTOT];   // 64 MB
__device__ __half g_Wt16[(long long)N4 * KTOT];     // 16 MB, [n][k] K-major

// ===================== helpers =====================
__device__ __forceinline__ uint32_t smem_u32(const void* p) {
    uint32_t a;
    asm("{ .reg .u64 t; cvta.to.shared.u64 t, %1; cvt.u32.u64 %0, t; }" : "=r"(a) : "l"(p));
    return a;
}
__device__ __forceinline__ void cp_async16(uint32_t dst, const void* src) {
    asm volatile("cp.async.cg.shared.global [%0], [%1], 16;" :: "r"(dst), "l"(src));
}
__device__ __forceinline__ void ldsm_x4(uint32_t& r0, uint32_t& r1, uint32_t& r2, uint32_t& r3,
                                        uint32_t addr) {
    asm volatile("ldmatrix.sync.aligned.m8n8.x4.shared.b16 {%0,%1,%2,%3}, [%4];"
                 : "=r"(r0), "=r"(r1), "=r"(r2), "=r"(r3) : "r"(addr));
}
__device__ __forceinline__ void mma16816(float& d0, float& d1, float& d2, float& d3,
                                         uint32_t a0, uint32_t a1, uint32_t a2, uint32_t a3,
                                         uint32_t b0, uint32_t b1) {
    asm volatile("mma.sync.aligned.m16n8k16.row.col.f32.f16.f16.f32 "
                 "{%0,%1,%2,%3}, {%4,%5,%6,%7}, {%8,%9}, {%0,%1,%2,%3};"
                 : "+f"(d0), "+f"(d1), "+f"(d2), "+f"(d3)
                 : "r"(a0), "r"(a1), "r"(a2), "r"(a3), "r"(b0), "r"(b1));
}
__device__ __forceinline__ float fsigm(float v) { return 1.0f / (1.0f + __expf(-v)); }
__device__ __forceinline__ float ftanh(float v) { return 2.0f / (1.0f + __expf(-2.0f * v)) - 1.0f; }

// ===================== merged prologue =====================
// blocks [0, NA): convert A to fp16.  blocks [NA, NA+NW): transpose+convert W.
static constexpr int NA_BLOCKS = (int)(((long long)BATCH * KTOT / 8) / 256);  // 16384
static constexpr int NW_X = N4 / 32;   // 128
static constexpr int NW_Y = KTOT / 32; // 64

__global__ __launch_bounds__(256) void conv_aw(const float* __restrict__ x,
                                               const float* __restrict__ state,
                                               const float* __restrict__ Wx,
                                               const float* __restrict__ Wh) {
    int bid = blockIdx.x;
    if (bid < NA_BLOCKS) {
        long long idx8 = ((long long)bid * 256 + threadIdx.x) * 8;
        int b = (int)(idx8 >> 11);
        int k = (int)(idx8 & 2047);
        const float* src = (k < H) ? (x + (long long)b * H + k)
                                   : (state + (long long)b * H + (k - H));
        float4 f0 = *reinterpret_cast<const float4*>(src);
        float4 f1 = *reinterpret_cast<const float4*>(src + 4);
        __half2 h[4];
        h[0] = __floats2half2_rn(f0.x, f0.y);
        h[1] = __floats2half2_rn(f0.z, f0.w);
        h[2] = __floats2half2_rn(f1.x, f1.y);
        h[3] = __floats2half2_rn(f1.z, f1.w);
        *reinterpret_cast<uint4*>(&g_A16[idx8]) = *reinterpret_cast<uint4*>(h);
    } else {
        __shared__ float tile[32][33];
        int wb = bid - NA_BLOCKS;
        int n0 = (wb % NW_X) * 32;
        int k0 = (wb / NW_X) * 32;
        int tx = threadIdx.x & 31, ty = threadIdx.x >> 5;   // ty 0..7
#pragma unroll
        for (int i = 0; i < 32; i += 8) {
            int k = k0 + ty + i;
            const float* src = (k < H) ? (Wx + (long long)k * N4) : (Wh + (long long)(k - H) * N4);
            tile[ty + i][tx] = src[n0 + tx];
        }
        __syncthreads();
#pragma unroll
        for (int i = 0; i < 32; i += 8) {
            g_Wt16[(long long)(n0 + ty + i) * KTOT + k0 + tx] = __float2half_rn(tile[tx][ty + i]);
        }
    }
}

// ===================== fused LSTM GEMM + gates =====================
// B smem layout (gate-interleaved, BN=128 rows of 64 halves):
//   row r: warpN=r>>5, gate=(r>>3)&3, i=r&7  ->  n = gate*H + c0 + warpN*8 + i
// Warp tile N=32: nb in {0,1} n16 blocks; gate = nb*2 + h2.
// Pipeline (per chunk): bar.sync -> ks0 -> load(c+2)+commit -> wait_group(1)
// -> ks1..ks3.  Main loop unrolled x3 so stage offsets are compile-time
// constants (stage of chunk c = c%3; loop runs over groups of 3).
__global__ __launch_bounds__(NTHREADS, 2) void lstm_fused(
    const float* __restrict__ cell, const float* __restrict__ bx,
    const float* __restrict__ bh, float* __restrict__ out)
{
    extern __shared__ char smem_raw[];
    __shared__ float bsum[BN];   // [gate][32] bias for this CTA's gate-col chunk

    const uint32_t sbase = smem_u32(smem_raw);
    int tid = threadIdx.x;
    int lane = tid & 31, wid = tid >> 5;
    int warpM = wid >> 2;            // 0..1, 64 rows each
    int warpN = wid & 3;             // 0..3, 8 gate-cols each (x4 gates)
    int m0 = blockIdx.y * BM;
    int c0 = blockIdx.x * GC;

    if (tid < BN) {   // bsum[g*32 + u] = bx[g*H + c0+u] + bh[g*H + c0+u]
        int g = tid >> 5, u = tid & 31;
        bsum[tid] = bx[g * H + c0 + u] + bh[g * H + c0 + u];
    }

    // --------- stage loader (256 threads) ---------
    auto load_stage = [&](int stage, int c) {
        uint32_t sA = sbase + stage * STAGE_BYTES;
        uint32_t sB = sA + A_BYTES;
        const __half* srcA = g_A16 + (long long)m0 * KTOT + c * KC;
        const __half* srcB = g_Wt16 + c * KC;
#pragma unroll
        for (int i = 0; i < 4; ++i) {           // A: 1024 segs of 16B
            int idx = tid + i * NTHREADS;
            int row = idx >> 3, seg = idx & 7;
            cp_async16(sA + row * 128 + ((seg ^ (row & 7)) * 16),
                       srcA + (long long)row * KTOT + seg * 8);
        }
#pragma unroll
        for (int i = 0; i < 4; ++i) {           // B: 1024 segs
            int idx = tid + i * NTHREADS;
            int r = idx >> 3, seg = idx & 7;
            int gate = (r >> 3) & 3;
            int colc = ((r >> 5) << 3) | (r & 7);
            int n = gate * H + c0 + colc;
            cp_async16(sB + r * 128 + ((seg ^ (r & 7)) * 16),
                       srcB + (long long)n * KTOT + seg * 8);
        }
        asm volatile("cp.async.commit_group;" ::: "memory");
    };

    // prologue loads: stages 0..STAGES-2, then retire chunk 0 early
    load_stage(0, 0);
    load_stage(1, 1);
    asm volatile("cp.async.wait_group %0;" :: "n"(STAGES - 2) : "memory");  // chunk 0 landed

    float acc[4][2][2][4];   // [mi][nb][h2][4]; gate = nb*2 + h2
#pragma unroll
    for (int mi = 0; mi < 4; ++mi)
#pragma unroll
        for (int nb = 0; nb < 2; ++nb)
#pragma unroll
            for (int h2 = 0; h2 < 2; ++h2)
#pragma unroll
                for (int e = 0; e < 4; ++e) acc[mi][nb][h2][e] = 0.0f;

    // lane-fixed address components
    int rowA = warpM * 64 + (lane & 15);              // + mi*16
    int kslA = (lane >> 4);                           // 0/1 -> +8 halves
    int nB   = warpN * 32 + ((lane >> 4) & 1) * 8 + (lane & 7);   // + nb*16
    int kslB = (lane >> 3) & 1;

    // one ks-slice of compute: LDSM fragments + 8 HMMA
    auto compute_ks = [&](uint32_t sA, uint32_t sB, int ks) {
        uint32_t a[4][4];
#pragma unroll
        for (int mi = 0; mi < 4; ++mi) {
            int row = rowA + mi * 16;
            int seg = (ks * 2 + kslA) ^ (row & 7);
            ldsm_x4(a[mi][0], a[mi][1], a[mi][2], a[mi][3], sA + row * 128 + seg * 16);
        }
        uint32_t b[2][4];
#pragma unroll
        for (int nb = 0; nb < 2; ++nb) {
            int n = nB + nb * 16;
            int seg = (ks * 2 + kslB) ^ (n & 7);
            ldsm_x4(b[nb][0], b[nb][1], b[nb][2], b[nb][3], sB + n * 128 + seg * 16);
        }
#pragma unroll
        for (int mi = 0; mi < 4; ++mi)
#pragma unroll
            for (int nb = 0; nb < 2; ++nb) {
                mma16816(acc[mi][nb][0][0], acc[mi][nb][0][1], acc[mi][nb][0][2], acc[mi][nb][0][3],
                         a[mi][0], a[mi][1], a[mi][2], a[mi][3], b[nb][0], b[nb][1]);
                mma16816(acc[mi][nb][1][0], acc[mi][nb][1][1], acc[mi][nb][1][2], acc[mi][nb][1][3],
                         a[mi][0], a[mi][1], a[mi][2], a[mi][3], b[nb][2], b[nb][3]);
            }
    };

    // --------- main loop: groups of 3 chunks, stages 0/1/2 compile-time ---------
    // NCHUNK-2 = 30 chunks with a distance-2 load; chunks 30, 31 are the tail.
#pragma unroll 1
    for (int cbase = 0; cbase < NCHUNK - 2; cbase += 3) {
#pragma unroll
        for (int s = 0; s < 3; ++s) {          // unrolled: s, stages constant
            int c = cbase + s;
            // CTA-wide rendezvous. Release implies:
            //  - every thread's chunk-c copies landed (wait ran before arrival)
            //  - all chunk c-1 reads done -> stage (s+2)%3 free for loads below
            __syncthreads();
            uint32_t sA = sbase + s * STAGE_BYTES;    // constant offset
            uint32_t sB = sA + A_BYTES;
            compute_ks(sA, sB, 0);
            load_stage((s + 2) % 3, c + 2);           // constant stage
            // retire chunk c+1 mid-chunk: pending {c+1, c+2} -> {c+2}
            asm volatile("cp.async.wait_group %0;" :: "n"(STAGES - 2) : "memory");
            compute_ks(sA, sB, 1);
            compute_ks(sA, sB, 2);
            compute_ks(sA, sB, 3);
        }
    }

    // --------- tail: chunk 30 (stage 0), chunk 31 (stage 1), no loads ---------
    {
        __syncthreads();                               // chunk 30 data landed
        uint32_t sA = sbase + 0 * STAGE_BYTES;
        uint32_t sB = sA + A_BYTES;
        compute_ks(sA, sB, 0);
        // retire chunk 31 (last pending group) off the barrier path
        asm volatile("cp.async.wait_group 0;" ::: "memory");
        compute_ks(sA, sB, 1);
        compute_ks(sA, sB, 2);
        compute_ks(sA, sB, 3);
    }
    {
        __syncthreads();                               // chunk 31 data landed (all threads)
        uint32_t sA = sbase + 1 * STAGE_BYTES;
        uint32_t sB = sA + A_BYTES;
        compute_ks(sA, sB, 0);
        compute_ks(sA, sB, 1);
        compute_ks(sA, sB, 2);
        compute_ks(sA, sB, 3);
    }

    // --------- register-direct fused gate epilogue ---------
    // gate g = nb*2+h2: gi=(0,0), gj=(0,1), gf=(1,0), go=(1,1)
    int ucol = warpN * 8 + (lane & 3) * 2;
    float bi[2], bj[2], bf[2], bo[2];
#pragma unroll
    for (int e = 0; e < 2; ++e) {
        int u = ucol + e;
        bi[e] = bsum[0  + u];
        bj[e] = bsum[32 + u];
        bf[e] = bsum[64 + u];
        bo[e] = bsum[96 + u];
    }

    int row0 = m0 + warpM * 64 + (lane >> 2);   // + mi*16 + p*8
    long long colg = c0 + ucol;
#pragma unroll
    for (int mi = 0; mi < 4; ++mi) {
#pragma unroll
        for (int p = 0; p < 2; ++p) {       // p=0 -> elems 0,1; p=1 -> elems 2,3
            int row = row0 + mi * 16 + p * 8;
            long long off = (long long)row * H + colg;
            float2 cv = *reinterpret_cast<const float2*>(cell + off);
            float outS[2], outC[2];
#pragma unroll
            for (int e = 0; e < 2; ++e) {
                float gi = acc[mi][0][0][p * 2 + e] + bi[e];
                float gj = acc[mi][0][1][p * 2 + e] + bj[e];
                float gf = acc[mi][1][0][p * 2 + e] + bf[e];
                float go = acc[mi][1][1][p * 2 + e] + bo[e];
                float iv = ftanh(gi);
                float jv = fsigm(gj);
                float fv = fsigm(gf);
                float ov = ftanh(go);
                float cdv = (e ? cv.y : cv.x) * fv + iv * jv;
                outC[e] = cdv;
                outS[e] = ftanh(cdv) * ov;
            }
            *reinterpret_cast<float2*>(out + off) = make_float2(outS[0], outS[1]);
            *reinterpret_cast<float2*>(out + (long long)BATCH * H + off) =
                make_float2(outC[0], outC[1]);
        }
    }
}

// ===================== launch =====================
extern "C" void kernel_launch(void* const* d_in, const int* in_sizes, int n_in,
                              void* d_out, int out_size) {
    (void)in_sizes; (void)n_in; (void)out_size;
    const float* x     = (const float*)d_in[0];
    const float* state = (const float*)d_in[1];
    const float* cell  = (const float*)d_in[2];
    const float* Wx    = (const float*)d_in[3];
    const float* bx    = (const float*)d_in[4];
    const float* Wh    = (const float*)d_in[5];
    const float* bh    = (const float*)d_in[6];
    float* out = (float*)d_out;

    conv_aw<<<NA_BLOCKS + NW_X * NW_Y, 256>>>(x, state, Wx, Wh);

    cudaFuncSetAttribute(lstm_fused, cudaFuncAttributeMaxDynamicSharedMemorySize, SMEM_DYN);
    lstm_fused<<<dim3(H / GC, BATCH / BM), NTHREADS, SMEM_DYN>>>(cell, bx, bh, out);
}